// round 2
// baseline (speedup 1.0000x reference)
#include <cuda_runtime.h>

// _QuantumLSTMCell: analytic collapse of the 4-qubit circuit.
// angles = comb @ W^T + b ; z_w = cos(angle_w + th_w)
// E0 = z1 z2 z3 ; E1 = z0 z1 ; E2 = z0 z1 z2 ; E3 = z0 z1 z2 z3
// f,i,o = sigmoid(E), g = tanh(E_u); c' = f*cx + i*g; h' = o*tanh(c')
// out = [h_new (B*4) | c_new (B*4)]

#define THREADS 256
#define D_COLS 256          // x feature dim
#define NKP 130             // 260 / 2 k-pairs
#define NJ 16               // 4 gates * 4 wires

typedef unsigned long long u64;

__device__ __forceinline__ u64 pk(float lo, float hi) {
    u64 r; asm("mov.b64 %0, {%1,%2};" : "=l"(r) : "f"(lo), "f"(hi)); return r;
}
__device__ __forceinline__ void upk(u64 v, float& lo, float& hi) {
    asm("mov.b64 {%0,%1}, %2;" : "=f"(lo), "=f"(hi) : "l"(v));
}
// packed dual-FMA: d.lo += a.lo*b.lo ; d.hi += a.hi*b.hi  (sm_10x f32x2 pipe)
__device__ __forceinline__ void fma2(u64& d, u64 a, u64 b) {
    asm("fma.rn.f32x2 %0, %1, %2, %0;" : "+l"(d) : "l"(a), "l"(b));
}

__device__ __forceinline__ float sigmoidf_(float x) {
    return 1.0f / (1.0f + __expf(-x));
}
__device__ __forceinline__ float tanhf_(float x) {
    return 1.0f - 2.0f / (__expf(2.0f * x) + 1.0f);
}

__global__ void __launch_bounds__(THREADS, 3)
qlstm_kernel(const float* __restrict__ x, const float* __restrict__ hx,
             const float* __restrict__ cx,
             const float* __restrict__ Wf, const float* __restrict__ bf,
             const float* __restrict__ Wi, const float* __restrict__ bi,
             const float* __restrict__ Wu, const float* __restrict__ bu,
             const float* __restrict__ Wo, const float* __restrict__ bo,
             const float* __restrict__ tf, const float* __restrict__ ti,
             const float* __restrict__ tu, const float* __restrict__ to,
             float* __restrict__ out, int B)
{
    // packed weights: sw[kpair*16 + j] = (W_j[2k], W_j[2k+1]), j = gate*4 + wire
    __shared__ __align__(16) u64 sw[NKP * NJ];
    __shared__ float sphase[NJ];

    for (int i = threadIdx.x; i < NKP * NJ; i += THREADS) {
        int t = i >> 4, j = i & 15;
        int g = j >> 2, w = j & 3;
        const float* W = (g == 0) ? Wf : (g == 1) ? Wi : (g == 2) ? Wu : Wo;
        const float* row = W + w * 260 + 2 * t;
        sw[i] = pk(row[0], row[1]);
    }
    if (threadIdx.x < NJ) {
        int j = threadIdx.x, g = j >> 2, w = j & 3;
        const float* bb = (g == 0) ? bf : (g == 1) ? bi : (g == 2) ? bu : bo;
        const float* tt = (g == 0) ? tf : (g == 1) ? ti : (g == 2) ? tu : to;
        sphase[j] = bb[w] + tt[w];
    }
    __syncthreads();

    int r = blockIdx.x * THREADS + threadIdx.x;
    if (r >= B) return;

    // x row as packed f32x2 pairs: bit layout of two adjacent floats == f32x2
    const ulonglong2* xr = (const ulonglong2*)(x + (size_t)r * D_COLS); // 64 entries
    const ulonglong2* swv = (const ulonglong2*)sw;   // [NKP/2 groups][16]

    u64 acc[NJ];
#pragma unroll
    for (int j = 0; j < NJ; j++) acc[j] = 0ull;

    // 64 x-vectors (4 floats each) = 128 k-pairs; process 4 per outer iter,
    // front-batched LDGs for MLP.
#pragma unroll 1
    for (int t = 0; t < 64; t += 4) {
        ulonglong2 a0 = xr[t + 0];
        ulonglong2 a1 = xr[t + 1];
        ulonglong2 a2 = xr[t + 2];
        ulonglong2 a3 = xr[t + 3];
#pragma unroll
        for (int u = 0; u < 4; u++) {
            ulonglong2 a = (u == 0) ? a0 : (u == 1) ? a1 : (u == 2) ? a2 : a3;
            const ulonglong2* wv = swv + (size_t)(t + u) * 16;
#pragma unroll
            for (int jj = 0; jj < 8; jj++) {
                ulonglong2 w = wv[jj];            // k-pair 2(t+u), j=2jj,2jj+1
                fma2(acc[2 * jj],     a.x, w.x);
                fma2(acc[2 * jj + 1], a.x, w.y);
            }
#pragma unroll
            for (int jj = 0; jj < 8; jj++) {
                ulonglong2 w = wv[8 + jj];        // k-pair 2(t+u)+1
                fma2(acc[2 * jj],     a.y, w.x);
                fma2(acc[2 * jj + 1], a.y, w.y);
            }
        }
    }
    // hx tail: k = 256..259 -> k-pairs 128, 129 (ulonglong2 group 64)
    {
        ulonglong2 a = ((const ulonglong2*)hx)[r];
        const ulonglong2* wv = swv + (size_t)64 * 16;
#pragma unroll
        for (int jj = 0; jj < 8; jj++) {
            ulonglong2 w = wv[jj];
            fma2(acc[2 * jj],     a.x, w.x);
            fma2(acc[2 * jj + 1], a.x, w.y);
        }
#pragma unroll
        for (int jj = 0; jj < 8; jj++) {
            ulonglong2 w = wv[8 + jj];
            fma2(acc[2 * jj],     a.y, w.x);
            fma2(acc[2 * jj + 1], a.y, w.y);
        }
    }

    // epilogue
    float z[NJ];
#pragma unroll
    for (int j = 0; j < NJ; j++) {
        float lo, hi; upk(acc[j], lo, hi);
        z[j] = __cosf(lo + hi + sphase[j]);
    }
    float e[NJ];
#pragma unroll
    for (int g = 0; g < 4; g++) {
        float z0 = z[g*4+0], z1 = z[g*4+1], z2 = z[g*4+2], z3 = z[g*4+3];
        float p01 = z0 * z1;
        e[g*4+0] = z1 * z2 * z3;
        e[g*4+1] = p01;
        e[g*4+2] = p01 * z2;
        e[g*4+3] = p01 * z2 * z3;
    }
    float4 cxv = ((const float4*)cx)[r];
    float cxa[4] = {cxv.x, cxv.y, cxv.z, cxv.w};
    float hn[4], cn[4];
#pragma unroll
    for (int w = 0; w < 4; w++) {
        float fv = sigmoidf_(e[0*4+w]);
        float iv = sigmoidf_(e[1*4+w]);
        float gv = tanhf_(e[2*4+w]);
        float ov = sigmoidf_(e[3*4+w]);
        float c = fv * cxa[w] + iv * gv;
        cn[w] = c;
        hn[w] = ov * tanhf_(c);
    }

    ((float4*)out)[r]                      = make_float4(hn[0], hn[1], hn[2], hn[3]);
    ((float4*)(out + (size_t)B * 4))[r]    = make_float4(cn[0], cn[1], cn[2], cn[3]);
}

extern "C" void kernel_launch(void* const* d_in, const int* in_sizes, int n_in,
                              void* d_out, int out_size) {
    const float* x  = (const float*)d_in[0];
    const float* hx = (const float*)d_in[1];
    const float* cx = (const float*)d_in[2];
    const float* Wf = (const float*)d_in[3];
    const float* bf = (const float*)d_in[4];
    const float* Wi = (const float*)d_in[5];
    const float* bi = (const float*)d_in[6];
    const float* Wu = (const float*)d_in[7];
    const float* bu = (const float*)d_in[8];
    const float* Wo = (const float*)d_in[9];
    const float* bo = (const float*)d_in[10];
    const float* tf = (const float*)d_in[11];
    const float* ti = (const float*)d_in[12];
    const float* tu = (const float*)d_in[13];
    const float* to = (const float*)d_in[14];
    float* out = (float*)d_out;

    int B = in_sizes[0] / D_COLS;                 // 131072
    int grid = (B + THREADS - 1) / THREADS;       // 512

    qlstm_kernel<<<grid, THREADS>>>(x, hx, cx, Wf, bf, Wi, bi, Wu, bu, Wo, bo,
                                    tf, ti, tu, to, out, B);
}

// round 3
// speedup vs baseline: 1.1193x; 1.1193x over previous
#include <cuda_runtime.h>

// _QuantumLSTMCell: analytic collapse of the 4-qubit circuit.
// angles = comb @ W^T + b ; z_w = cos(angle_w + th_w)
// E0 = z1 z2 z3 ; E1 = z0 z1 ; E2 = z0 z1 z2 ; E3 = z0 z1 z2 z3
// f,i,o = sigmoid(E), g = tanh(E_u); c' = f*cx + i*g; h' = o*tanh(c')
// out = [h_new (B*4) | c_new (B*4)]

#define THREADS 128
#define RPT 4               // rows per thread
#define D_COLS 256
#define NJ 16               // 4 gates * 4 wires

typedef unsigned long long u64;

__device__ __forceinline__ u64 pk(float lo, float hi) {
    u64 r; asm("mov.b64 %0, {%1,%2};" : "=l"(r) : "f"(lo), "f"(hi)); return r;
}
__device__ __forceinline__ void upk(u64 v, float& lo, float& hi) {
    asm("mov.b64 {%0,%1}, %2;" : "=f"(lo), "=f"(hi) : "l"(v));
}
// packed dual-FMA: d.lo += a.lo*b.lo ; d.hi += a.hi*b.hi
__device__ __forceinline__ void fma2(u64& d, u64 a, u64 b) {
    asm("fma.rn.f32x2 %0, %1, %2, %0;" : "+l"(d) : "l"(a), "l"(b));
}

__device__ __forceinline__ float sigmoidf_(float x) {
    return 1.0f / (1.0f + __expf(-x));
}
__device__ __forceinline__ float tanhf_(float x) {
    return 1.0f - 2.0f / (__expf(2.0f * x) + 1.0f);
}

// process one k (scalar x value per row) against all 16 j
__device__ __forceinline__ void do_k(u64 acc[RPT][8], const float xv[RPT],
                                     const ulonglong2* __restrict__ wk) {
    ulonglong2 wa = wk[0], wb = wk[1], wc = wk[2], wd = wk[3]; // j 0..15
#pragma unroll
    for (int r = 0; r < RPT; r++) {
        u64 s = pk(xv[r], xv[r]);
        fma2(acc[r][0], s, wa.x); fma2(acc[r][1], s, wa.y);
        fma2(acc[r][2], s, wb.x); fma2(acc[r][3], s, wb.y);
        fma2(acc[r][4], s, wc.x); fma2(acc[r][5], s, wc.y);
        fma2(acc[r][6], s, wd.x); fma2(acc[r][7], s, wd.y);
    }
}

__global__ void __launch_bounds__(THREADS, 4)
qlstm_kernel(const float* __restrict__ x, const float* __restrict__ hx,
             const float* __restrict__ cx,
             const float* __restrict__ Wf, const float* __restrict__ bf,
             const float* __restrict__ Wi, const float* __restrict__ bi,
             const float* __restrict__ Wu, const float* __restrict__ bu,
             const float* __restrict__ Wo, const float* __restrict__ bo,
             const float* __restrict__ tf, const float* __restrict__ ti,
             const float* __restrict__ tu, const float* __restrict__ to,
             float* __restrict__ out, int B)
{
    // weights j-major per k: swf[k*16 + j], j = gate*4 + wire
    __shared__ __align__(16) float swf[260 * NJ];
    __shared__ float sphase[NJ];

    for (int i = threadIdx.x; i < 260 * NJ; i += THREADS) {
        int k = i >> 4, j = i & 15;
        int g = j >> 2, w = j & 3;
        const float* W = (g == 0) ? Wf : (g == 1) ? Wi : (g == 2) ? Wu : Wo;
        swf[i] = W[w * 260 + k];
    }
    if (threadIdx.x < NJ) {
        int j = threadIdx.x, g = j >> 2, w = j & 3;
        const float* bb = (g == 0) ? bf : (g == 1) ? bi : (g == 2) ? bu : bo;
        const float* tt = (g == 0) ? tf : (g == 1) ? ti : (g == 2) ? tu : to;
        sphase[j] = bb[w] + tt[w];
    }
    __syncthreads();

    const ulonglong2* swv = (const ulonglong2*)swf;   // [k][4]

    int r0 = (blockIdx.x * THREADS + threadIdx.x) * RPT;
    if (r0 + RPT > B) return;

    const float4* xp0 = (const float4*)(x + (size_t)(r0 + 0) * D_COLS);
    const float4* xp1 = (const float4*)(x + (size_t)(r0 + 1) * D_COLS);
    const float4* xp2 = (const float4*)(x + (size_t)(r0 + 2) * D_COLS);
    const float4* xp3 = (const float4*)(x + (size_t)(r0 + 3) * D_COLS);

    u64 acc[RPT][8];
#pragma unroll
    for (int r = 0; r < RPT; r++)
#pragma unroll
        for (int jj = 0; jj < 8; jj++) acc[r][jj] = 0ull;

    // 64 k-quads over x
#pragma unroll 2
    for (int t = 0; t < D_COLS / 4; ++t) {
        float4 v0 = xp0[t], v1 = xp1[t], v2 = xp2[t], v3 = xp3[t];
        const ulonglong2* wk = swv + (size_t)t * 16;  // 4 k * 4 u64x2
        float xv[RPT];
        xv[0] = v0.x; xv[1] = v1.x; xv[2] = v2.x; xv[3] = v3.x;
        do_k(acc, xv, wk + 0);
        xv[0] = v0.y; xv[1] = v1.y; xv[2] = v2.y; xv[3] = v3.y;
        do_k(acc, xv, wk + 4);
        xv[0] = v0.z; xv[1] = v1.z; xv[2] = v2.z; xv[3] = v3.z;
        do_k(acc, xv, wk + 8);
        xv[0] = v0.w; xv[1] = v1.w; xv[2] = v2.w; xv[3] = v3.w;
        do_k(acc, xv, wk + 12);
    }
    // hx tail: k = 256..259
    {
        float4 h0 = ((const float4*)hx)[r0 + 0];
        float4 h1 = ((const float4*)hx)[r0 + 1];
        float4 h2 = ((const float4*)hx)[r0 + 2];
        float4 h3 = ((const float4*)hx)[r0 + 3];
        const ulonglong2* wk = swv + (size_t)64 * 16;
        float xv[RPT];
        xv[0] = h0.x; xv[1] = h1.x; xv[2] = h2.x; xv[3] = h3.x;
        do_k(acc, xv, wk + 0);
        xv[0] = h0.y; xv[1] = h1.y; xv[2] = h2.y; xv[3] = h3.y;
        do_k(acc, xv, wk + 4);
        xv[0] = h0.z; xv[1] = h1.z; xv[2] = h2.z; xv[3] = h3.z;
        do_k(acc, xv, wk + 8);
        xv[0] = h0.w; xv[1] = h1.w; xv[2] = h2.w; xv[3] = h3.w;
        do_k(acc, xv, wk + 12);
    }

    // epilogue per row
#pragma unroll
    for (int r = 0; r < RPT; r++) {
        float z[NJ];
#pragma unroll
        for (int jj = 0; jj < 8; jj++) {
            float lo, hi; upk(acc[r][jj], lo, hi);
            z[2 * jj]     = __cosf(lo + sphase[2 * jj]);
            z[2 * jj + 1] = __cosf(hi + sphase[2 * jj + 1]);
        }
        float e[NJ];
#pragma unroll
        for (int g = 0; g < 4; g++) {
            float z0 = z[g*4+0], z1 = z[g*4+1], z2 = z[g*4+2], z3 = z[g*4+3];
            float p01 = z0 * z1;
            e[g*4+0] = z1 * z2 * z3;
            e[g*4+1] = p01;
            e[g*4+2] = p01 * z2;
            e[g*4+3] = p01 * z2 * z3;
        }
        float4 cxv = ((const float4*)cx)[r0 + r];
        float cxa[4] = {cxv.x, cxv.y, cxv.z, cxv.w};
        float hn[4], cn[4];
#pragma unroll
        for (int w = 0; w < 4; w++) {
            float fv = sigmoidf_(e[0*4+w]);
            float iv = sigmoidf_(e[1*4+w]);
            float gv = tanhf_(e[2*4+w]);
            float ov = sigmoidf_(e[3*4+w]);
            float c = fv * cxa[w] + iv * gv;
            cn[w] = c;
            hn[w] = ov * tanhf_(c);
        }
        ((float4*)out)[r0 + r] = make_float4(hn[0], hn[1], hn[2], hn[3]);
        ((float4*)(out + (size_t)B * 4))[r0 + r] = make_float4(cn[0], cn[1], cn[2], cn[3]);
    }
}

extern "C" void kernel_launch(void* const* d_in, const int* in_sizes, int n_in,
                              void* d_out, int out_size) {
    const float* x  = (const float*)d_in[0];
    const float* hx = (const float*)d_in[1];
    const float* cx = (const float*)d_in[2];
    const float* Wf = (const float*)d_in[3];
    const float* bf = (const float*)d_in[4];
    const float* Wi = (const float*)d_in[5];
    const float* bi = (const float*)d_in[6];
    const float* Wu = (const float*)d_in[7];
    const float* bu = (const float*)d_in[8];
    const float* Wo = (const float*)d_in[9];
    const float* bo = (const float*)d_in[10];
    const float* tf = (const float*)d_in[11];
    const float* ti = (const float*)d_in[12];
    const float* tu = (const float*)d_in[13];
    const float* to = (const float*)d_in[14];
    float* out = (float*)d_out;

    int B = in_sizes[0] / D_COLS;                      // 131072
    int grid = (B + THREADS * RPT - 1) / (THREADS * RPT);  // 256

    qlstm_kernel<<<grid, THREADS>>>(x, hx, cx, Wf, bf, Wi, bi, Wu, bu, Wo, bo,
                                    tf, ti, tu, to, out, B);
}

// round 4
// speedup vs baseline: 1.2598x; 1.1255x over previous
#include <cuda_runtime.h>

// _QuantumLSTMCell: analytic collapse of the 4-qubit circuit.
// angles = comb @ W^T + b ; z_w = cos(angle_w + th_w)
// E0 = z1 z2 z3 ; E1 = z0 z1 ; E2 = z0 z1 z2 ; E3 = z0 z1 z2 z3
// f,i,o = sigmoid(E), g = tanh(E_u); c' = f*cx + i*g; h' = o*tanh(c')
// out = [h_new (B*4) | c_new (B*4)]
//
// R4: cp.async double-buffered x staging (fixes nL=32 LDG wavefront storm),
// lane-interleaved row ownership (conflict-free tile reads, coalesced
// cx/hx/out), RPT=4 weight-LDS amortization kept.

#define THREADS 128
#define RPT 4
#define ROWS_BLK (THREADS * RPT)     // 512
#define D_COLS 256
#define NJ 16
#define TILE_K 16
#define NTILES (D_COLS / TILE_K)     // 16
#define PITCH 20                     // floats per row in x tile (80 B)
#define XS_STAGE_F (ROWS_BLK * PITCH)   // 10240 floats per stage
#define SWF_F (260 * NJ)             // 4160 floats
#define SMEM_FLOATS (SWF_F + 2 * XS_STAGE_F + NJ)
#define SMEM_BYTES (SMEM_FLOATS * 4) // 98624 B

typedef unsigned long long u64;

__device__ __forceinline__ u64 pk(float lo, float hi) {
    u64 r; asm("mov.b64 %0, {%1,%2};" : "=l"(r) : "f"(lo), "f"(hi)); return r;
}
__device__ __forceinline__ void upk(u64 v, float& lo, float& hi) {
    asm("mov.b64 {%0,%1}, %2;" : "=f"(lo), "=f"(hi) : "l"(v));
}
__device__ __forceinline__ void fma2(u64& d, u64 a, u64 b) {
    asm("fma.rn.f32x2 %0, %1, %2, %0;" : "+l"(d) : "l"(a), "l"(b));
}
__device__ __forceinline__ void cp16(unsigned dst, const void* src) {
    asm volatile("cp.async.cg.shared.global [%0], [%1], 16;" :: "r"(dst), "l"(src));
}
__device__ __forceinline__ void cp_commit() {
    asm volatile("cp.async.commit_group;");
}
__device__ __forceinline__ void cp_wait1() {
    asm volatile("cp.async.wait_group 1;");
}
__device__ __forceinline__ void cp_wait0() {
    asm volatile("cp.async.wait_group 0;");
}

__device__ __forceinline__ float sigmoidf_(float x) {
    return 1.0f / (1.0f + __expf(-x));
}
__device__ __forceinline__ float tanhf_(float x) {
    return 1.0f - 2.0f / (__expf(2.0f * x) + 1.0f);
}

// one k (scalar x per row) against all 16 j
__device__ __forceinline__ void do_k(u64 acc[RPT][8], const float xv[RPT],
                                     const ulonglong2* __restrict__ wk) {
    ulonglong2 wa = wk[0], wb = wk[1], wc = wk[2], wd = wk[3]; // j 0..15
#pragma unroll
    for (int r = 0; r < RPT; r++) {
        u64 s = pk(xv[r], xv[r]);
        fma2(acc[r][0], s, wa.x); fma2(acc[r][1], s, wa.y);
        fma2(acc[r][2], s, wb.x); fma2(acc[r][3], s, wb.y);
        fma2(acc[r][4], s, wc.x); fma2(acc[r][5], s, wc.y);
        fma2(acc[r][6], s, wd.x); fma2(acc[r][7], s, wd.y);
    }
}

__global__ void __launch_bounds__(THREADS)
qlstm_kernel(const float* __restrict__ x, const float* __restrict__ hx,
             const float* __restrict__ cx,
             const float* __restrict__ Wf, const float* __restrict__ bf,
             const float* __restrict__ Wi, const float* __restrict__ bi,
             const float* __restrict__ Wu, const float* __restrict__ bu,
             const float* __restrict__ Wo, const float* __restrict__ bo,
             const float* __restrict__ tf, const float* __restrict__ ti,
             const float* __restrict__ tu, const float* __restrict__ to,
             float* __restrict__ out, int B)
{
    extern __shared__ float smem[];
    float* swf    = smem;                      // [260][16] j-major per k
    float* xs     = smem + SWF_F;              // [2][512][PITCH]
    float* sphase = smem + SWF_F + 2 * XS_STAGE_F;

    const int tid = threadIdx.x;
    const int row0 = blockIdx.x * ROWS_BLK;
    const float* xblk = x + (size_t)row0 * D_COLS;

    // ---- issue tile 0 and 1 immediately (before weight staging) ----
    unsigned xs_s = (unsigned)__cvta_generic_to_shared(xs);
#pragma unroll
    for (int stg = 0; stg < 2; stg++) {
#pragma unroll
        for (int i = 0; i < (ROWS_BLK * TILE_K / 4) / THREADS; i++) {  // 16
            int c  = i * THREADS + tid;       // 0..2047 16B-chunks
            int rl = c >> 2, kq = c & 3;
            cp16(xs_s + (unsigned)((stg * XS_STAGE_F + rl * PITCH + kq * 4) * 4),
                 xblk + (size_t)rl * D_COLS + stg * TILE_K + kq * 4);
        }
        cp_commit();
    }

    // ---- stage weights (one-time) ----
    for (int i = tid; i < SWF_F; i += THREADS) {
        int k = i >> 4, j = i & 15;
        int g = j >> 2, w = j & 3;
        const float* W = (g == 0) ? Wf : (g == 1) ? Wi : (g == 2) ? Wu : Wo;
        swf[i] = W[w * 260 + k];
    }
    if (tid < NJ) {
        int j = tid, g = j >> 2, w = j & 3;
        const float* bb = (g == 0) ? bf : (g == 1) ? bi : (g == 2) ? bu : bo;
        const float* tt = (g == 0) ? tf : (g == 1) ? ti : (g == 2) ? tu : to;
        sphase[j] = bb[w] + tt[w];
    }

    const ulonglong2* swv2 = (const ulonglong2*)swf;  // [k][4]

    u64 acc[RPT][8];
#pragma unroll
    for (int r = 0; r < RPT; r++)
#pragma unroll
        for (int jj = 0; jj < 8; jj++) acc[r][jj] = 0ull;

    // ---- main pipelined loop over k-tiles ----
#pragma unroll 1
    for (int t = 0; t < NTILES; t++) {
        if (t == NTILES - 1) cp_wait0(); else cp_wait1();
        __syncthreads();

        const float* xb = xs + (t & 1) * XS_STAGE_F;
#pragma unroll
        for (int kq = 0; kq < 4; kq++) {
            float4 xv[RPT];
#pragma unroll
            for (int rr = 0; rr < RPT; rr++) {
                int rl = tid + 128 * rr;
                xv[rr] = *(const float4*)(xb + rl * PITCH + kq * 4);
            }
#pragma unroll
            for (int e = 0; e < 4; e++) {
                int k = t * TILE_K + kq * 4 + e;
                const ulonglong2* wk = swv2 + (size_t)k * 4;
                float s[RPT];
#pragma unroll
                for (int rr = 0; rr < RPT; rr++)
                    s[rr] = ((const float*)&xv[rr])[e];
                do_k(acc, s, wk);
            }
        }
        __syncthreads();

        if (t + 2 < NTILES) {
            int nt = t + 2;
#pragma unroll
            for (int i = 0; i < (ROWS_BLK * TILE_K / 4) / THREADS; i++) {
                int c  = i * THREADS + tid;
                int rl = c >> 2, kq = c & 3;
                cp16(xs_s + (unsigned)(((t & 1) * XS_STAGE_F + rl * PITCH + kq * 4) * 4),
                     xblk + (size_t)rl * D_COLS + nt * TILE_K + kq * 4);
            }
            cp_commit();
        }
    }

    // ---- hx tail: k = 256..259 (coalesced: lanes -> consecutive rows) ----
    {
        float4 hv[RPT];
#pragma unroll
        for (int rr = 0; rr < RPT; rr++)
            hv[rr] = ((const float4*)hx)[row0 + tid + 128 * rr];
#pragma unroll
        for (int e = 0; e < 4; e++) {
            const ulonglong2* wk = swv2 + (size_t)(256 + e) * 4;
            float s[RPT];
#pragma unroll
            for (int rr = 0; rr < RPT; rr++)
                s[rr] = ((const float*)&hv[rr])[e];
            do_k(acc, s, wk);
        }
    }

    // ---- epilogue per row ----
#pragma unroll
    for (int rr = 0; rr < RPT; rr++) {
        int r = row0 + tid + 128 * rr;
        float z[NJ];
#pragma unroll
        for (int jj = 0; jj < 8; jj++) {
            float lo, hi; upk(acc[rr][jj], lo, hi);
            z[2 * jj]     = __cosf(lo + sphase[2 * jj]);
            z[2 * jj + 1] = __cosf(hi + sphase[2 * jj + 1]);
        }
        float e[NJ];
#pragma unroll
        for (int g = 0; g < 4; g++) {
            float z0 = z[g*4+0], z1 = z[g*4+1], z2 = z[g*4+2], z3 = z[g*4+3];
            float p01 = z0 * z1;
            e[g*4+0] = z1 * z2 * z3;
            e[g*4+1] = p01;
            e[g*4+2] = p01 * z2;
            e[g*4+3] = p01 * z2 * z3;
        }
        float4 cxv = ((const float4*)cx)[r];
        float cxa[4] = {cxv.x, cxv.y, cxv.z, cxv.w};
        float hn[4], cn[4];
#pragma unroll
        for (int w = 0; w < 4; w++) {
            float fv = sigmoidf_(e[0*4+w]);
            float iv = sigmoidf_(e[1*4+w]);
            float gv = tanhf_(e[2*4+w]);
            float ov = sigmoidf_(e[3*4+w]);
            float c = fv * cxa[w] + iv * gv;
            cn[w] = c;
            hn[w] = ov * tanhf_(c);
        }
        ((float4*)out)[r] = make_float4(hn[0], hn[1], hn[2], hn[3]);
        ((float4*)(out + (size_t)B * 4))[r] = make_float4(cn[0], cn[1], cn[2], cn[3]);
    }
}

extern "C" void kernel_launch(void* const* d_in, const int* in_sizes, int n_in,
                              void* d_out, int out_size) {
    const float* x  = (const float*)d_in[0];
    const float* hx = (const float*)d_in[1];
    const float* cx = (const float*)d_in[2];
    const float* Wf = (const float*)d_in[3];
    const float* bf = (const float*)d_in[4];
    const float* Wi = (const float*)d_in[5];
    const float* bi = (const float*)d_in[6];
    const float* Wu = (const float*)d_in[7];
    const float* bu = (const float*)d_in[8];
    const float* Wo = (const float*)d_in[9];
    const float* bo = (const float*)d_in[10];
    const float* tf = (const float*)d_in[11];
    const float* ti = (const float*)d_in[12];
    const float* tu = (const float*)d_in[13];
    const float* to = (const float*)d_in[14];
    float* out = (float*)d_out;

    int B = in_sizes[0] / D_COLS;                 // 131072
    int grid = (B + ROWS_BLK - 1) / ROWS_BLK;     // 256

    cudaFuncSetAttribute(qlstm_kernel,
                         cudaFuncAttributeMaxDynamicSharedMemorySize, SMEM_BYTES);

    qlstm_kernel<<<grid, THREADS, SMEM_BYTES>>>(
        x, hx, cx, Wf, bf, Wi, bi, Wu, bu, Wo, bo,
        tf, ti, tu, to, out, B);
}